// round 14
// baseline (speedup 1.0000x reference)
#include <cuda_runtime.h>
#include <cuda_bf16.h>
#include <math.h>
#include <stdint.h>

#define BB 128
#define TT 512
#define FF 16
#define HH 32

// ---------------- scratch ----------------
__device__ float d_xpe[BB * TT * 48];
__device__ float d_h  [BB * TT * FF];
__device__ float d_ht [FF * BB * TT];            // transposed encoder output [f][b][t]
__device__ float d_u1 [(size_t)FF * BB * TT * 64];
__device__ float d_xp2[(size_t)FF * BB * TT * 96];
__device__ float d_v2 [(size_t)FF * BB * TT * 32];
__device__ float d_a3 [(size_t)FF * BB * TT * 64];
__device__ float d_a2 [(size_t)FF * BB * TT * 128];

__device__ __nv_bfloat16 d_w3h[16 * 64 * 160];
__device__ __nv_bfloat16 d_w3l[16 * 64 * 160];
__device__ __nv_bfloat16 d_w2h[16 * 128 * 320];
__device__ __nv_bfloat16 d_w2l[16 * 128 * 320];

__device__ __forceinline__ float sigmoidf_(float x) {
    return 1.0f / (1.0f + __expf(-x));
}
__device__ __forceinline__ float tanhf_(float x) {
    float ax = fabsf(x);
    float e  = __expf(-2.0f * ax);
    float t  = (1.0f - e) / (1.0f + e);
    return copysignf(t, x);
}
__device__ __forceinline__ float leaky_(float v) {
    return v >= 0.0f ? v : 0.01f * v;
}

// ---------------- tensor-core helpers ----------------
__device__ __forceinline__ void mma16816(float* c, const uint32_t* a, const uint32_t* b) {
    asm volatile(
        "mma.sync.aligned.m16n8k16.row.col.f32.bf16.bf16.f32 "
        "{%0,%1,%2,%3},{%4,%5,%6,%7},{%8,%9},{%0,%1,%2,%3};"
        : "+f"(c[0]), "+f"(c[1]), "+f"(c[2]), "+f"(c[3])
        : "r"(a[0]), "r"(a[1]), "r"(a[2]), "r"(a[3]), "r"(b[0]), "r"(b[1]));
}
__device__ __forceinline__ uint32_t ld2bf(const __nv_bfloat16* p) {
    return *(const uint32_t*)p;
}
__device__ __forceinline__ void cp16(void* dst, const void* src) {
    uint32_t d = (uint32_t)__cvta_generic_to_shared(dst);
    asm volatile("cp.async.ca.shared.global [%0],[%1],16;" :: "r"(d), "l"(src));
}
#define CP_COMMIT() asm volatile("cp.async.commit_group;")
#define CP_WAIT0()  asm volatile("cp.async.wait_group 0;")
#define CP_WAIT1()  asm volatile("cp.async.wait_group 1;")

__device__ __forceinline__ void split_bf16(float v, __nv_bfloat16& hi, __nv_bfloat16& lo) {
    hi = __float2bfloat16(v);
    lo = __float2bfloat16(v - __bfloat162float(hi));
}

// ---------------- weight pre-split ----------------
__global__ void k_wprep(const float* __restrict__ w3, const float* __restrict__ w2) {
    int idx = blockIdx.x * blockDim.x + threadIdx.x;
    const int N3 = 16 * 64 * 160;
    const int N2 = 16 * 128 * 320;
    if (idx < N3) {
        int f  = idx / (64 * 160);
        int r  = idx % (64 * 160);
        int co = r / 160;
        int k  = r % 160;
        int kp = k / 32, ci = k % 32;
        float v = w3[((size_t)(f * 32 + ci) * 64 + co) * 5 + (4 - kp)];
        split_bf16(v, d_w3h[idx], d_w3l[idx]);
    } else if (idx < N3 + N2) {
        int j  = idx - N3;
        int f  = j / (128 * 320);
        int r  = j % (128 * 320);
        int co = r / 320;
        int k  = r % 320;
        int kp = k / 64, ci = k % 64;
        float v = w2[((size_t)(f * 64 + ci) * 128 + co) * 5 + (4 - kp)];
        split_bf16(v, d_w2h[j], d_w2l[j]);
    }
}

// ---------------- encoder input projection ----------------
__global__ void k_enc_xp(const float* __restrict__ x,
                         const float* __restrict__ Wih,
                         const float* __restrict__ bih) {
    int idx = blockIdx.x * blockDim.x + threadIdx.x;
    if (idx >= BB * TT * 48) return;
    int g  = idx % 48;
    int bt = idx / 48;
    int b  = bt / TT;
    int t  = bt % TT;
    float x0 = x[b * 2 * TT + t];
    float x1 = x[b * 2 * TT + TT + t];
    d_xpe[idx] = x0 * Wih[g * 2] + x1 * Wih[g * 2 + 1] + bih[g];
}

// ---------------- encoder GRU recurrence (one warp per batch, 3041 build) ----------------
__global__ void k_enc_rec(const float* __restrict__ Whh,
                          const float* __restrict__ bhh) {
    int warp = (blockIdx.x * blockDim.x + threadIdx.x) >> 5;
    int l    = threadIdx.x & 31;
    if (warp >= BB) return;
    int b = warp;

    float w0[16], w1[16];
#pragma unroll
    for (int k = 0; k < 16; k++) {
        w0[k] = Whh[l * 16 + k];
        w1[k] = (l < 16) ? Whh[(32 + l) * 16 + k] : 0.0f;
    }
    float bh0 = bhh[l];
    float bh1 = (l < 16) ? bhh[32 + l] : 0.0f;

    float h = 0.0f;
    const float* xp = d_xpe + (size_t)b * TT * 48;
    float* ho = d_h + (size_t)b * TT * FF;

    for (int t = 0; t < TT; t++) {
        float xpa = xp[t * 48 + l];
        float xpn = (l < 16) ? xp[t * 48 + 32 + l] : 0.0f;
        float a0 = bh0, a1 = bh1;
#pragma unroll
        for (int k = 0; k < 16; k++) {
            float hk = __shfl_sync(0xffffffffu, h, k);
            a0 += hk * w0[k];
            a1 += hk * w1[k];
        }
        float g = sigmoidf_(xpa + a0);
        float z = __shfl_sync(0xffffffffu, g, l + 16);
        if (l < 16) {
            float n = tanhf_(xpn + g * a1);
            h = (1.0f - z) * n + z * h;
            ho[t * FF + l] = h;
        }
    }
}

// ---------------- transpose d_h -> d_ht[f][b][t] ----------------
__global__ void k_htr() {
    int idx = blockIdx.x * blockDim.x + threadIdx.x;   // (f*BB+b)*TT + t
    if (idx >= FF * BB * TT) return;
    int t  = idx & (TT - 1);
    int fb = idx >> 9;
    int b  = fb & (BB - 1);
    int f  = fb >> 7;
    d_ht[idx] = d_h[((size_t)b * TT + t) * FF + f];
}

// ---------------- biGRU: ILP-1, rep-2, sequential xi + 2-step prefetch ----------------
__global__ __launch_bounds__(256, 2) void k_g1(
    const float* __restrict__ Wih_f, const float* __restrict__ Whh_f,
    const float* __restrict__ bih_f, const float* __restrict__ bhh_f,
    const float* __restrict__ Wih_b, const float* __restrict__ Whh_b,
    const float* __restrict__ bih_b, const float* __restrict__ bhh_b) {
    int gw0 = (blockIdx.x * 256 + threadIdx.x) >> 5;   // 0..2047
    int l   = threadIdx.x & 31;

    for (int rep = 0; rep < 2; rep++) {
        int gw  = gw0 + rep * 2048;                    // 0..4095
        int b   = gw & (BB - 1);
        int f   = (gw >> 7) & (FF - 1);
        int dir = gw >> 11;

        const float* Wih = dir ? Wih_b : Wih_f;
        const float* Whh = dir ? Whh_b : Whh_f;
        const float* bih = dir ? bih_b : bih_f;
        const float* bhh = dir ? bhh_b : bhh_f;

        float wr[32], wz[32], wn[32];
        const float* Wr = Whh + (size_t)(f * 96 + l) * 32;
        const float* Wz = Whh + (size_t)(f * 96 + 32 + l) * 32;
        const float* Wn = Whh + (size_t)(f * 96 + 64 + l) * 32;
#pragma unroll
        for (int k = 0; k < 32; k++) { wr[k] = Wr[k]; wz[k] = Wz[k]; wn[k] = Wn[k]; }

        float wir = Wih[f * 96 + l], wiz = Wih[f * 96 + 32 + l], win = Wih[f * 96 + 64 + l];
        float br  = bih[f * 96 + l], bz  = bih[f * 96 + 32 + l], bn  = bih[f * 96 + 64 + l];
        float cr  = bhh[f * 96 + l], cz  = bhh[f * 96 + 32 + l], cn  = bhh[f * 96 + 64 + l];

        float h = 0.0f;
        const float* hin = d_ht + (size_t)(f * BB + b) * TT;   // sequential in t
        float* u = d_u1 + (size_t)(f * BB + b) * TT * 64 + dir * 32 + l;

        int t0 = dir ? (TT - 1) : 0;
        int t1 = dir ? (TT - 2) : 1;
        float xi   = hin[t0];
        float xi_n = hin[t1];

        for (int s = 0; s < TT; s++) {
            int t   = dir ? (TT - 1 - s) : s;
            int tnn = dir ? (TT - 3 - s) : (s + 2);
            // prefetch 2 steps ahead before the serial gate math
            float xi_nn = (s + 2 < TT) ? hin[tnn] : 0.0f;

            float ar = cr, az = cz, an = cn;
#pragma unroll
            for (int k = 0; k < 32; k++) {
                float hk = __shfl_sync(0xffffffffu, h, k);
                ar += hk * wr[k];
                az += hk * wz[k];
                an += hk * wn[k];
            }
            float r = sigmoidf_(xi * wir + br + ar);
            float z = sigmoidf_(xi * wiz + bz + az);
            float n = tanhf_(xi * win + bn + r * an);
            h = (1.0f - z) * n + z * h;
            u[(size_t)t * 64] = h;
            xi = xi_n;
            xi_n = xi_nn;
        }
    }
}

// ---------------- g2 input projection, tensor cores (3041 build) ----------------
__global__ __launch_bounds__(256) void k_xp2_tc(const float* __restrict__ Wih2,
                                                const float* __restrict__ bih2) {
    extern __shared__ __nv_bfloat16 smx[];
    __nv_bfloat16* sAh = smx;
    __nv_bfloat16* sAl = smx + 128 * 72;
    __nv_bfloat16* sBh = smx + 2 * 128 * 72;
    __nv_bfloat16* sBl = sBh + 96 * 72;

    int f  = blockIdx.y;
    int r0 = blockIdx.x * 128;
    int tid = threadIdx.x;
    int wid = tid >> 5, l = tid & 31;
    int wt = wid >> 1, wc = wid & 1;

    const float* A  = d_u1 + (size_t)f * BB * TT * 64 + (size_t)r0 * 64;
    const float* Wb = Wih2 + (size_t)f * 96 * 64;

    for (int i = tid; i < 128 * 16; i += 256) {
        int rr = i >> 4, kq = i & 15;
        float4 v = *(const float4*)&A[(size_t)rr * 64 + kq * 4];
        __nv_bfloat16 h0, l0, h1, l1, h2, l2, h3, l3;
        split_bf16(v.x, h0, l0); split_bf16(v.y, h1, l1);
        split_bf16(v.z, h2, l2); split_bf16(v.w, h3, l3);
        __nv_bfloat16* ph = sAh + rr * 72 + kq * 4;
        __nv_bfloat16* pl = sAl + rr * 72 + kq * 4;
        ph[0] = h0; ph[1] = h1; ph[2] = h2; ph[3] = h3;
        pl[0] = l0; pl[1] = l1; pl[2] = l2; pl[3] = l3;
    }
    for (int i = tid; i < 96 * 16; i += 256) {
        int j = i >> 4, kq = i & 15;
        float4 v = *(const float4*)&Wb[(size_t)j * 64 + kq * 4];
        __nv_bfloat16 h0, l0, h1, l1, h2, l2, h3, l3;
        split_bf16(v.x, h0, l0); split_bf16(v.y, h1, l1);
        split_bf16(v.z, h2, l2); split_bf16(v.w, h3, l3);
        __nv_bfloat16* ph = sBh + j * 72 + kq * 4;
        __nv_bfloat16* pl = sBl + j * 72 + kq * 4;
        ph[0] = h0; ph[1] = h1; ph[2] = h2; ph[3] = h3;
        pl[0] = l0; pl[1] = l1; pl[2] = l2; pl[3] = l3;
    }
    __syncthreads();

    float acc[2][6][4];
#pragma unroll
    for (int mt = 0; mt < 2; mt++)
#pragma unroll
        for (int nt = 0; nt < 6; nt++)
#pragma unroll
            for (int q = 0; q < 4; q++) acc[mt][nt][q] = 0.0f;

    int q4 = 2 * (l & 3);
    int r4 = l >> 2;

#pragma unroll
    for (int kt = 0; kt < 4; kt++) {
        int col = kt * 16 + q4;
        uint32_t Ah[2][4], Al[2][4];
#pragma unroll
        for (int mt = 0; mt < 2; mt++) {
            int row = wt * 32 + mt * 16 + r4;
            const __nv_bfloat16* ph = sAh + row * 72 + col;
            const __nv_bfloat16* pl = sAl + row * 72 + col;
            Ah[mt][0] = ld2bf(ph);       Ah[mt][1] = ld2bf(ph + 8 * 72);
            Ah[mt][2] = ld2bf(ph + 8);   Ah[mt][3] = ld2bf(ph + 8 * 72 + 8);
            Al[mt][0] = ld2bf(pl);       Al[mt][1] = ld2bf(pl + 8 * 72);
            Al[mt][2] = ld2bf(pl + 8);   Al[mt][3] = ld2bf(pl + 8 * 72 + 8);
        }
#pragma unroll
        for (int nt = 0; nt < 6; nt++) {
            int co = wc * 48 + nt * 8 + r4;
            uint32_t Bh[2], Bl[2];
            const __nv_bfloat16* pb = sBh + co * 72 + col;
            const __nv_bfloat16* pc = sBl + co * 72 + col;
            Bh[0] = ld2bf(pb); Bh[1] = ld2bf(pb + 8);
            Bl[0] = ld2bf(pc); Bl[1] = ld2bf(pc + 8);
#pragma unroll
            for (int mt = 0; mt < 2; mt++) {
                mma16816(acc[mt][nt], Ah[mt], Bh);
                mma16816(acc[mt][nt], Ah[mt], Bl);
                mma16816(acc[mt][nt], Al[mt], Bh);
            }
        }
    }

    float* C = d_xp2 + (size_t)f * BB * TT * 96 + (size_t)r0 * 96;
#pragma unroll
    for (int nt = 0; nt < 6; nt++) {
        int co = wc * 48 + nt * 8 + q4;
        float b0 = bih2[f * 96 + co], b1 = bih2[f * 96 + co + 1];
#pragma unroll
        for (int mt = 0; mt < 2; mt++) {
            int r = wt * 32 + mt * 16 + r4;
            float2 v0 = make_float2(acc[mt][nt][0] + b0, acc[mt][nt][1] + b1);
            float2 v1 = make_float2(acc[mt][nt][2] + b0, acc[mt][nt][3] + b1);
            *(float2*)&C[(size_t)r * 96 + co] = v0;
            *(float2*)&C[(size_t)(r + 8) * 96 + co] = v1;
        }
    }
}

// ---------------- g2 recurrence: ILP-1, 2048 warps + 2-step prefetch ----------------
__global__ __launch_bounds__(256, 2) void k_g2(const float* __restrict__ Whh2,
                                               const float* __restrict__ bhh2) {
    int gw = (blockIdx.x * 256 + threadIdx.x) >> 5;   // 0..2047
    int l  = threadIdx.x & 31;
    int b = gw & (BB - 1);
    int f = gw >> 7;                                   // 0..15

    float wr[32], wz[32], wn[32];
    const float* Wr = Whh2 + (size_t)(f * 96 + l) * 32;
    const float* Wz = Whh2 + (size_t)(f * 96 + 32 + l) * 32;
    const float* Wn = Whh2 + (size_t)(f * 96 + 64 + l) * 32;
#pragma unroll
    for (int k = 0; k < 32; k++) { wr[k] = Wr[k]; wz[k] = Wz[k]; wn[k] = Wn[k]; }
    float cr = bhh2[f * 96 + l], cz = bhh2[f * 96 + 32 + l], cn = bhh2[f * 96 + 64 + l];

    float h = 0.0f;
    const float* XP = d_xp2 + ((size_t)f * BB + b) * TT * 96;
    float* V = d_v2 + ((size_t)f * BB + b) * TT * 32 + l;

    float xr = XP[l], xz = XP[32 + l], xn = XP[64 + l];
    float xr1 = XP[96 + l], xz1 = XP[96 + 32 + l], xn1 = XP[96 + 64 + l];

    for (int t = 0; t < TT; t++) {
        // prefetch 2 steps ahead before the serial gate math
        float xr2 = 0.0f, xz2 = 0.0f, xn2 = 0.0f;
        if (t + 2 < TT) {
            const float* xt2 = XP + (size_t)(t + 2) * 96;
            xr2 = xt2[l];
            xz2 = xt2[32 + l];
            xn2 = xt2[64 + l];
        }
        float ar = cr, az = cz, an = cn;
#pragma unroll
        for (int k = 0; k < 32; k++) {
            float hk = __shfl_sync(0xffffffffu, h, k);
            ar += hk * wr[k];
            az += hk * wz[k];
            an += hk * wn[k];
        }
        float r = sigmoidf_(xr + ar);
        float z = sigmoidf_(xz + az);
        float n = tanhf_(xn + r * an);
        h = (1.0f - z) * n + z * h;
        V[(size_t)t * 32] = h;
        xr = xr1; xz = xz1; xn = xn1;
        xr1 = xr2; xz1 = xz2; xn1 = xn2;
    }
}

// ---------------- convT 32->64, tensor cores (3041 build) ----------------
__global__ __launch_bounds__(256) void k_conv3_tc(const float* __restrict__ b3) {
    extern __shared__ __nv_bfloat16 sm3[];
    __nv_bfloat16* sxh = sm3;
    __nv_bfloat16* sxl = sm3 + 132 * 40;
    __nv_bfloat16* sbh = sm3 + 2 * 132 * 40;
    __nv_bfloat16* sbl = sbh + 64 * 168;

    int f = blockIdx.z, b = blockIdx.y, t0 = blockIdx.x * 128;
    int tid = threadIdx.x;
    int wid = tid >> 5, l = tid & 31;
    int wt = wid >> 1, wc = wid & 1;

    for (int i = tid; i < 2560; i += 256) {
        int split = i / 1280;
        int r = i % 1280;
        int co = r / 20, seg = r % 20;
        const __nv_bfloat16* src = (split ? d_w3l : d_w3h) + ((size_t)(f * 64 + co)) * 160 + seg * 8;
        __nv_bfloat16* dst = (split ? sbl : sbh) + co * 168 + seg * 8;
        cp16(dst, src);
    }
    CP_COMMIT();

    const float* X = d_v2 + ((size_t)f * BB + b) * TT * 32;
    for (int i = tid; i < 132 * 32; i += 256) {
        int tt = i >> 5, ci = i & 31;
        int t = t0 - 2 + tt;
        float v = (t >= 0 && t < TT) ? X[(size_t)t * 32 + ci] : 0.0f;
        __nv_bfloat16 hi, lo;
        split_bf16(v, hi, lo);
        sxh[tt * 40 + ci] = hi;
        sxl[tt * 40 + ci] = lo;
    }
    CP_WAIT0();
    __syncthreads();

    float acc[2][4][4];
#pragma unroll
    for (int mt = 0; mt < 2; mt++)
#pragma unroll
        for (int nt = 0; nt < 4; nt++)
#pragma unroll
            for (int q = 0; q < 4; q++) acc[mt][nt][q] = 0.0f;

    int q4 = 2 * (l & 3);
    int r4 = l >> 2;

#pragma unroll
    for (int s = 0; s < 10; s++) {
        int kp = s >> 1;
        int col = (s & 1) * 16 + q4;
        uint32_t Ah[2][4], Al[2][4];
#pragma unroll
        for (int mt = 0; mt < 2; mt++) {
            int row = wt * 32 + mt * 16 + r4 + kp;
            const __nv_bfloat16* ph = sxh + row * 40 + col;
            const __nv_bfloat16* pl = sxl + row * 40 + col;
            Ah[mt][0] = ld2bf(ph);            Ah[mt][1] = ld2bf(ph + 8 * 40);
            Ah[mt][2] = ld2bf(ph + 8);        Ah[mt][3] = ld2bf(ph + 8 * 40 + 8);
            Al[mt][0] = ld2bf(pl);            Al[mt][1] = ld2bf(pl + 8 * 40);
            Al[mt][2] = ld2bf(pl + 8);        Al[mt][3] = ld2bf(pl + 8 * 40 + 8);
        }
        int bk = s * 16 + q4;
#pragma unroll
        for (int nt = 0; nt < 4; nt++) {
            int co = wc * 32 + nt * 8 + r4;
            uint32_t Bh[2], Bl[2];
            const __nv_bfloat16* pb = sbh + co * 168 + bk;
            const __nv_bfloat16* pc = sbl + co * 168 + bk;
            Bh[0] = ld2bf(pb); Bh[1] = ld2bf(pb + 8);
            Bl[0] = ld2bf(pc); Bl[1] = ld2bf(pc + 8);
#pragma unroll
            for (int mt = 0; mt < 2; mt++) {
                mma16816(acc[mt][nt], Ah[mt], Bh);
                mma16816(acc[mt][nt], Ah[mt], Bl);
                mma16816(acc[mt][nt], Al[mt], Bh);
            }
        }
    }

    float* Y = d_a3 + (((size_t)f * BB + b) * TT + t0) * 64;
#pragma unroll
    for (int nt = 0; nt < 4; nt++) {
        int co = wc * 32 + nt * 8 + q4;
        float b0 = b3[f * 64 + co], b1 = b3[f * 64 + co + 1];
#pragma unroll
        for (int mt = 0; mt < 2; mt++) {
            int t = wt * 32 + mt * 16 + r4;
            float2 v0 = make_float2(leaky_(acc[mt][nt][0] + b0), leaky_(acc[mt][nt][1] + b1));
            float2 v1 = make_float2(leaky_(acc[mt][nt][2] + b0), leaky_(acc[mt][nt][3] + b1));
            *(float2*)&Y[(size_t)t * 64 + co] = v0;
            *(float2*)&Y[(size_t)(t + 8) * 64 + co] = v1;
        }
    }
}

// ---------------- convT 64->128, tensor cores (3041 build) ----------------
__global__ __launch_bounds__(256) void k_conv2_tc(const float* __restrict__ b2) {
    extern __shared__ __nv_bfloat16 sm2[];
    __nv_bfloat16* sxh = sm2;
    __nv_bfloat16* sxl = sm2 + 132 * 72;
    __nv_bfloat16* sbb = sm2 + 2 * 132 * 72;

    int f = blockIdx.z, b = blockIdx.y, t0 = blockIdx.x * 128;
    int tid = threadIdx.x;
    int wid = tid >> 5, l = tid & 31;
    int wt = wid >> 1, wc = wid & 1;

    int lco = tid >> 1, lhalf = tid & 1;
    const __nv_bfloat16* wsrc_h = d_w2h + ((size_t)f * 128 + lco) * 320 + lhalf * 8;
    const __nv_bfloat16* wsrc_l = d_w2l + ((size_t)f * 128 + lco) * 320 + lhalf * 8;
    __nv_bfloat16* wdst0 = sbb + lco * 24 + lhalf * 8;

    cp16(wdst0,        wsrc_h);
    cp16(wdst0 + 3072, wsrc_l);
    CP_COMMIT();

    const float* X = d_a3 + ((size_t)f * BB + b) * TT * 64;
    for (int i = tid; i < 132 * 64; i += 256) {
        int tt = i >> 6, ci = i & 63;
        int t = t0 - 2 + tt;
        float v = (t >= 0 && t < TT) ? X[(size_t)t * 64 + ci] : 0.0f;
        __nv_bfloat16 hi, lo;
        split_bf16(v, hi, lo);
        sxh[tt * 72 + ci] = hi;
        sxl[tt * 72 + ci] = lo;
    }
    __syncthreads();

    float acc[2][8][4];
#pragma unroll
    for (int mt = 0; mt < 2; mt++)
#pragma unroll
        for (int nt = 0; nt < 8; nt++)
#pragma unroll
            for (int q = 0; q < 4; q++) acc[mt][nt][q] = 0.0f;

    int q4 = 2 * (l & 3);
    int r4 = l >> 2;

    for (int s = 0; s < 20; s++) {
        if (s + 1 < 20) {
            __nv_bfloat16* wdst = sbb + ((s + 1) & 1) * 6144 + lco * 24 + lhalf * 8;
            cp16(wdst,        wsrc_h + (s + 1) * 16);
            cp16(wdst + 3072, wsrc_l + (s + 1) * 16);
        }
        CP_COMMIT();
        CP_WAIT1();
        __syncthreads();

        const __nv_bfloat16* sbh = sbb + (s & 1) * 6144;
        const __nv_bfloat16* sbl = sbh + 3072;
        int kp = s >> 2;
        int col = (s & 3) * 16 + q4;

        uint32_t Ah[2][4], Al[2][4];
#pragma unroll
        for (int mt = 0; mt < 2; mt++) {
            int row = wt * 32 + mt * 16 + r4 + kp;
            const __nv_bfloat16* ph = sxh + row * 72 + col;
            const __nv_bfloat16* pl = sxl + row * 72 + col;
            Ah[mt][0] = ld2bf(ph);            Ah[mt][1] = ld2bf(ph + 8 * 72);
            Ah[mt][2] = ld2bf(ph + 8);        Ah[mt][3] = ld2bf(ph + 8 * 72 + 8);
            Al[mt][0] = ld2bf(pl);            Al[mt][1] = ld2bf(pl + 8 * 72);
            Al[mt][2] = ld2bf(pl + 8);        Al[mt][3] = ld2bf(pl + 8 * 72 + 8);
        }
#pragma unroll
        for (int nt = 0; nt < 8; nt++) {
            int co = wc * 64 + nt * 8 + r4;
            uint32_t Bh[2], Bl[2];
            const __nv_bfloat16* pb = sbh + co * 24 + q4;
            const __nv_bfloat16* pc = sbl + co * 24 + q4;
            Bh[0] = ld2bf(pb); Bh[1] = ld2bf(pb + 8);
            Bl[0] = ld2bf(pc); Bl[1] = ld2bf(pc + 8);
#pragma unroll
            for (int mt = 0; mt < 2; mt++) {
                mma16816(acc[mt][nt], Ah[mt], Bh);
                mma16816(acc[mt][nt], Ah[mt], Bl);
                mma16816(acc[mt][nt], Al[mt], Bh);
            }
        }
        __syncthreads();
    }

    float* Y = d_a2 + (((size_t)f * BB + b) * TT + t0) * 128;
#pragma unroll
    for (int nt = 0; nt < 8; nt++) {
        int co = wc * 64 + nt * 8 + q4;
        float b0 = b2[f * 128 + co], b1v = b2[f * 128 + co + 1];
#pragma unroll
        for (int mt = 0; mt < 2; mt++) {
            int t = wt * 32 + mt * 16 + r4;
            float2 v0 = make_float2(leaky_(acc[mt][nt][0] + b0), leaky_(acc[mt][nt][1] + b1v));
            float2 v1 = make_float2(leaky_(acc[mt][nt][2] + b0), leaky_(acc[mt][nt][3] + b1v));
            *(float2*)&Y[(size_t)t * 128 + co] = v0;
            *(float2*)&Y[(size_t)(t + 8) * 128 + co] = v1;
        }
    }
}

// ---------------- convT 128 -> 1 + leaky, write final output (3041 build) ----------------
__global__ __launch_bounds__(64) void k_conv1(const float* __restrict__ w1,
                                              const float* __restrict__ b1,
                                              float* __restrict__ out) {
    __shared__ float sx[68][132];
    __shared__ float sw[5][128];
    int f = blockIdx.z, bb = blockIdx.y, t0 = blockIdx.x * 64;
    int tid = threadIdx.x;

    const float* X = d_a2 + ((size_t)f * BB + bb) * TT * 128;
    for (int i = tid; i < 68 * 128; i += 64) {
        int tt = i >> 7, ci = i & 127;
        int t = t0 - 2 + tt;
        sx[tt][ci] = (t >= 0 && t < TT) ? X[(size_t)t * 128 + ci] : 0.0f;
    }
    for (int i = tid; i < 5 * 128; i += 64) {
        int j = i >> 7, ci = i & 127;
        sw[j][ci] = w1[f * 640 + ci * 5 + (4 - j)];
    }
    __syncthreads();

    int tl = tid;
    float a0 = 0.0f, a1 = 0.0f, a2s = 0.0f, a3s = 0.0f;
#pragma unroll
    for (int j = 0; j < 5; j++) {
        const float* xr = &sx[tl + j][0];
        const float* wr_ = &sw[j][0];
#pragma unroll
        for (int ci = 0; ci < 128; ci += 4) {
            float4 a = *(const float4*)&xr[ci];
            float4 w = *(const float4*)&wr_[ci];
            a0 += a.x * w.x;
            a1 += a.y * w.y;
            a2s += a.z * w.z;
            a3s += a.w * w.w;
        }
    }
    float v = leaky_((a0 + a1) + (a2s + a3s) + b1[f]);
    out[((size_t)bb * TT + t0 + tl) * FF + f] = v;
}

// ---------------- launch ----------------
extern "C" void kernel_launch(void* const* d_in, const int* in_sizes, int n_in,
                              void* d_out, int out_size) {
    const float* x        = (const float*)d_in[0];
    const float* enc_Wih  = (const float*)d_in[1];
    const float* enc_Whh  = (const float*)d_in[2];
    const float* enc_bih  = (const float*)d_in[3];
    const float* enc_bhh  = (const float*)d_in[4];
    const float* g1_Wih_f = (const float*)d_in[5];
    const float* g1_Whh_f = (const float*)d_in[6];
    const float* g1_bih_f = (const float*)d_in[7];
    const float* g1_bhh_f = (const float*)d_in[8];
    const float* g1_Wih_b = (const float*)d_in[9];
    const float* g1_Whh_b = (const float*)d_in[10];
    const float* g1_bih_b = (const float*)d_in[11];
    const float* g1_bhh_b = (const float*)d_in[12];
    const float* g2_Wih   = (const float*)d_in[13];
    const float* g2_Whh   = (const float*)d_in[14];
    const float* g2_bih   = (const float*)d_in[15];
    const float* g2_bhh   = (const float*)d_in[16];
    const float* w3       = (const float*)d_in[17];
    const float* b3       = (const float*)d_in[18];
    const float* w2       = (const float*)d_in[19];
    const float* b2       = (const float*)d_in[20];
    const float* w1       = (const float*)d_in[21];
    const float* b1       = (const float*)d_in[22];
    float* out = (float*)d_out;

    const int SMEM3 = (2 * 132 * 40 + 2 * 64 * 168) * 2;     // 64128 B
    const int SMEM2 = (2 * 132 * 72 + 4 * 128 * 24) * 2;     // 62592 B
    const int SMEMX = (2 * 128 * 72 + 2 * 96 * 72) * 2;      // 64512 B
    static bool attr_set = false;
    if (!attr_set) {
        cudaFuncSetAttribute(k_conv3_tc, cudaFuncAttributeMaxDynamicSharedMemorySize, SMEM3);
        cudaFuncSetAttribute(k_conv2_tc, cudaFuncAttributeMaxDynamicSharedMemorySize, SMEM2);
        cudaFuncSetAttribute(k_xp2_tc,  cudaFuncAttributeMaxDynamicSharedMemorySize, SMEMX);
        attr_set = true;
    }

    k_wprep<<<(16 * 64 * 160 + 16 * 128 * 320 + 255) / 256, 256>>>(w3, w2);
    k_enc_xp<<<(BB * TT * 48 + 255) / 256, 256>>>(x, enc_Wih, enc_bih);
    k_enc_rec<<<32, 128>>>(enc_Whh, enc_bhh);
    k_htr<<<(FF * BB * TT + 255) / 256, 256>>>();
    k_g1<<<256, 256>>>(g1_Wih_f, g1_Whh_f, g1_bih_f, g1_bhh_f,
                       g1_Wih_b, g1_Whh_b, g1_bih_b, g1_bhh_b);
    {
        dim3 g(BB * TT / 128, FF);
        k_xp2_tc<<<g, 256, SMEMX>>>(g2_Wih, g2_bih);
    }
    k_g2<<<256, 256>>>(g2_Whh, g2_bhh);
    {
        dim3 g(TT / 128, BB, FF);
        k_conv3_tc<<<g, 256, SMEM3>>>(b3);
        k_conv2_tc<<<g, 256, SMEM2>>>(b2);
    }
    {
        dim3 g(TT / 64, BB, FF);
        k_conv1<<<g, 64>>>(w1, b1, out);
    }
}

// round 15
// speedup vs baseline: 1.0705x; 1.0705x over previous
#include <cuda_runtime.h>
#include <cuda_bf16.h>
#include <math.h>
#include <stdint.h>

#define BB 128
#define TT 512
#define FF 16
#define HH 32

// ---------------- scratch ----------------
__device__ float d_xpe[BB * TT * 48];
__device__ float d_h  [BB * TT * FF];
__device__ float d_u1 [(size_t)FF * BB * TT * 64];
__device__ float d_xp2[(size_t)FF * BB * TT * 96];
__device__ __nv_bfloat16 d_v2h[(size_t)FF * BB * TT * 32];   // g2 output, pre-split
__device__ __nv_bfloat16 d_v2l[(size_t)FF * BB * TT * 32];
__device__ __nv_bfloat16 d_a3h[(size_t)FF * BB * TT * 64];   // conv3 output, pre-split
__device__ __nv_bfloat16 d_a3l[(size_t)FF * BB * TT * 64];
__device__ float d_a2 [(size_t)FF * BB * TT * 128];

__device__ __nv_bfloat16 d_w3h[16 * 64 * 160];
__device__ __nv_bfloat16 d_w3l[16 * 64 * 160];
__device__ __nv_bfloat16 d_w2h[16 * 128 * 320];
__device__ __nv_bfloat16 d_w2l[16 * 128 * 320];

__device__ __forceinline__ float sigmoidf_(float x) {
    return 1.0f / (1.0f + __expf(-x));
}
__device__ __forceinline__ float tanhf_(float x) {
    float ax = fabsf(x);
    float e  = __expf(-2.0f * ax);
    float t  = (1.0f - e) / (1.0f + e);
    return copysignf(t, x);
}
__device__ __forceinline__ float leaky_(float v) {
    return v >= 0.0f ? v : 0.01f * v;
}

// ---------------- tensor-core helpers ----------------
__device__ __forceinline__ void mma16816(float* c, const uint32_t* a, const uint32_t* b) {
    asm volatile(
        "mma.sync.aligned.m16n8k16.row.col.f32.bf16.bf16.f32 "
        "{%0,%1,%2,%3},{%4,%5,%6,%7},{%8,%9},{%0,%1,%2,%3};"
        : "+f"(c[0]), "+f"(c[1]), "+f"(c[2]), "+f"(c[3])
        : "r"(a[0]), "r"(a[1]), "r"(a[2]), "r"(a[3]), "r"(b[0]), "r"(b[1]));
}
__device__ __forceinline__ uint32_t ld2bf(const __nv_bfloat16* p) {
    return *(const uint32_t*)p;
}
__device__ __forceinline__ void cp16(void* dst, const void* src) {
    uint32_t d = (uint32_t)__cvta_generic_to_shared(dst);
    asm volatile("cp.async.ca.shared.global [%0],[%1],16;" :: "r"(d), "l"(src));
}
#define CP_COMMIT() asm volatile("cp.async.commit_group;")
#define CP_WAIT0()  asm volatile("cp.async.wait_group 0;")
#define CP_WAIT1()  asm volatile("cp.async.wait_group 1;")

__device__ __forceinline__ void split_bf16(float v, __nv_bfloat16& hi, __nv_bfloat16& lo) {
    hi = __float2bfloat16(v);
    lo = __float2bfloat16(v - __bfloat162float(hi));
}
__device__ __forceinline__ uint32_t pack2(__nv_bfloat16 a, __nv_bfloat16 b) {
    __nv_bfloat162 t; t.x = a; t.y = b;
    return *(uint32_t*)&t;
}

// ---------------- weight pre-split ----------------
__global__ void k_wprep(const float* __restrict__ w3, const float* __restrict__ w2) {
    int idx = blockIdx.x * blockDim.x + threadIdx.x;
    const int N3 = 16 * 64 * 160;
    const int N2 = 16 * 128 * 320;
    if (idx < N3) {
        int f  = idx / (64 * 160);
        int r  = idx % (64 * 160);
        int co = r / 160;
        int k  = r % 160;
        int kp = k / 32, ci = k % 32;
        float v = w3[((size_t)(f * 32 + ci) * 64 + co) * 5 + (4 - kp)];
        split_bf16(v, d_w3h[idx], d_w3l[idx]);
    } else if (idx < N3 + N2) {
        int j  = idx - N3;
        int f  = j / (128 * 320);
        int r  = j % (128 * 320);
        int co = r / 320;
        int k  = r % 320;
        int kp = k / 64, ci = k % 64;
        float v = w2[((size_t)(f * 64 + ci) * 128 + co) * 5 + (4 - kp)];
        split_bf16(v, d_w2h[j], d_w2l[j]);
    }
}

// ---------------- encoder input projection ----------------
__global__ void k_enc_xp(const float* __restrict__ x,
                         const float* __restrict__ Wih,
                         const float* __restrict__ bih) {
    int idx = blockIdx.x * blockDim.x + threadIdx.x;
    if (idx >= BB * TT * 48) return;
    int g  = idx % 48;
    int bt = idx / 48;
    int b  = bt / TT;
    int t  = bt % TT;
    float x0 = x[b * 2 * TT + t];
    float x1 = x[b * 2 * TT + TT + t];
    d_xpe[idx] = x0 * Wih[g * 2] + x1 * Wih[g * 2 + 1] + bih[g];
}

// ---------------- encoder GRU recurrence ----------------
__global__ void k_enc_rec(const float* __restrict__ Whh,
                          const float* __restrict__ bhh) {
    int warp = (blockIdx.x * blockDim.x + threadIdx.x) >> 5;
    int l    = threadIdx.x & 31;
    if (warp >= BB) return;
    int b = warp;

    float w0[16], w1[16];
#pragma unroll
    for (int k = 0; k < 16; k++) {
        w0[k] = Whh[l * 16 + k];
        w1[k] = (l < 16) ? Whh[(32 + l) * 16 + k] : 0.0f;
    }
    float bh0 = bhh[l];
    float bh1 = (l < 16) ? bhh[32 + l] : 0.0f;

    float h = 0.0f;
    const float* xp = d_xpe + (size_t)b * TT * 48;
    float* ho = d_h + (size_t)b * TT * FF;

    for (int t = 0; t < TT; t++) {
        float xpa = xp[t * 48 + l];
        float xpn = (l < 16) ? xp[t * 48 + 32 + l] : 0.0f;
        float a0 = bh0, a1 = bh1;
#pragma unroll
        for (int k = 0; k < 16; k++) {
            float hk = __shfl_sync(0xffffffffu, h, k);
            a0 += hk * w0[k];
            a1 += hk * w1[k];
        }
        float g = sigmoidf_(xpa + a0);
        float z = __shfl_sync(0xffffffffu, g, l + 16);
        if (l < 16) {
            float n = tanhf_(xpn + g * a1);
            h = (1.0f - z) * n + z * h;
            ho[t * FF + l] = h;
        }
    }
}

// ---------------- biGRU: ILP-1, rep-2 + 1-step xi prefetch (R13) ----------------
__global__ __launch_bounds__(256, 2) void k_g1(
    const float* __restrict__ Wih_f, const float* __restrict__ Whh_f,
    const float* __restrict__ bih_f, const float* __restrict__ bhh_f,
    const float* __restrict__ Wih_b, const float* __restrict__ Whh_b,
    const float* __restrict__ bih_b, const float* __restrict__ bhh_b) {
    int gw0 = (blockIdx.x * 256 + threadIdx.x) >> 5;   // 0..2047
    int l   = threadIdx.x & 31;

    for (int rep = 0; rep < 2; rep++) {
        int gw  = gw0 + rep * 2048;                    // 0..4095
        int b   = gw & (BB - 1);
        int f   = (gw >> 7) & (FF - 1);
        int dir = gw >> 11;

        const float* Wih = dir ? Wih_b : Wih_f;
        const float* Whh = dir ? Whh_b : Whh_f;
        const float* bih = dir ? bih_b : bih_f;
        const float* bhh = dir ? bhh_b : bhh_f;

        float wr[32], wz[32], wn[32];
        const float* Wr = Whh + (size_t)(f * 96 + l) * 32;
        const float* Wz = Whh + (size_t)(f * 96 + 32 + l) * 32;
        const float* Wn = Whh + (size_t)(f * 96 + 64 + l) * 32;
#pragma unroll
        for (int k = 0; k < 32; k++) { wr[k] = Wr[k]; wz[k] = Wz[k]; wn[k] = Wn[k]; }

        float wir = Wih[f * 96 + l], wiz = Wih[f * 96 + 32 + l], win = Wih[f * 96 + 64 + l];
        float br  = bih[f * 96 + l], bz  = bih[f * 96 + 32 + l], bn  = bih[f * 96 + 64 + l];
        float cr  = bhh[f * 96 + l], cz  = bhh[f * 96 + 32 + l], cn  = bhh[f * 96 + 64 + l];

        float h = 0.0f;
        const float* hin = d_h + (size_t)b * TT * FF + f;
        float* u = d_u1 + (size_t)(f * BB + b) * TT * 64 + dir * 32 + l;

        int t0 = dir ? (TT - 1) : 0;
        float xi = hin[(size_t)t0 * FF];

        for (int s = 0; s < TT; s++) {
            int t  = dir ? (TT - 1 - s) : s;
            int tn = dir ? (TT - 2 - s) : (s + 1);
            float xi_n = (s + 1 < TT) ? hin[(size_t)tn * FF] : 0.0f;

            float ar = cr, az = cz, an = cn;
#pragma unroll
            for (int k = 0; k < 32; k++) {
                float hk = __shfl_sync(0xffffffffu, h, k);
                ar += hk * wr[k];
                az += hk * wz[k];
                an += hk * wn[k];
            }
            float r = sigmoidf_(xi * wir + br + ar);
            float z = sigmoidf_(xi * wiz + bz + az);
            float n = tanhf_(xi * win + bn + r * an);
            h = (1.0f - z) * n + z * h;
            u[(size_t)t * 64] = h;
            xi = xi_n;
        }
    }
}

// ---------------- g2 input projection, tensor cores ----------------
__global__ __launch_bounds__(256) void k_xp2_tc(const float* __restrict__ Wih2,
                                                const float* __restrict__ bih2) {
    extern __shared__ __nv_bfloat16 smx[];
    __nv_bfloat16* sAh = smx;
    __nv_bfloat16* sAl = smx + 128 * 72;
    __nv_bfloat16* sBh = smx + 2 * 128 * 72;
    __nv_bfloat16* sBl = sBh + 96 * 72;

    int f  = blockIdx.y;
    int r0 = blockIdx.x * 128;
    int tid = threadIdx.x;
    int wid = tid >> 5, l = tid & 31;
    int wt = wid >> 1, wc = wid & 1;

    const float* A  = d_u1 + (size_t)f * BB * TT * 64 + (size_t)r0 * 64;
    const float* Wb = Wih2 + (size_t)f * 96 * 64;

    for (int i = tid; i < 128 * 16; i += 256) {
        int rr = i >> 4, kq = i & 15;
        float4 v = *(const float4*)&A[(size_t)rr * 64 + kq * 4];
        __nv_bfloat16 h0, l0, h1, l1, h2, l2, h3, l3;
        split_bf16(v.x, h0, l0); split_bf16(v.y, h1, l1);
        split_bf16(v.z, h2, l2); split_bf16(v.w, h3, l3);
        __nv_bfloat16* ph = sAh + rr * 72 + kq * 4;
        __nv_bfloat16* pl = sAl + rr * 72 + kq * 4;
        ph[0] = h0; ph[1] = h1; ph[2] = h2; ph[3] = h3;
        pl[0] = l0; pl[1] = l1; pl[2] = l2; pl[3] = l3;
    }
    for (int i = tid; i < 96 * 16; i += 256) {
        int j = i >> 4, kq = i & 15;
        float4 v = *(const float4*)&Wb[(size_t)j * 64 + kq * 4];
        __nv_bfloat16 h0, l0, h1, l1, h2, l2, h3, l3;
        split_bf16(v.x, h0, l0); split_bf16(v.y, h1, l1);
        split_bf16(v.z, h2, l2); split_bf16(v.w, h3, l3);
        __nv_bfloat16* ph = sBh + j * 72 + kq * 4;
        __nv_bfloat16* pl = sBl + j * 72 + kq * 4;
        ph[0] = h0; ph[1] = h1; ph[2] = h2; ph[3] = h3;
        pl[0] = l0; pl[1] = l1; pl[2] = l2; pl[3] = l3;
    }
    __syncthreads();

    float acc[2][6][4];
#pragma unroll
    for (int mt = 0; mt < 2; mt++)
#pragma unroll
        for (int nt = 0; nt < 6; nt++)
#pragma unroll
            for (int q = 0; q < 4; q++) acc[mt][nt][q] = 0.0f;

    int q4 = 2 * (l & 3);
    int r4 = l >> 2;

#pragma unroll
    for (int kt = 0; kt < 4; kt++) {
        int col = kt * 16 + q4;
        uint32_t Ah[2][4], Al[2][4];
#pragma unroll
        for (int mt = 0; mt < 2; mt++) {
            int row = wt * 32 + mt * 16 + r4;
            const __nv_bfloat16* ph = sAh + row * 72 + col;
            const __nv_bfloat16* pl = sAl + row * 72 + col;
            Ah[mt][0] = ld2bf(ph);       Ah[mt][1] = ld2bf(ph + 8 * 72);
            Ah[mt][2] = ld2bf(ph + 8);   Ah[mt][3] = ld2bf(ph + 8 * 72 + 8);
            Al[mt][0] = ld2bf(pl);       Al[mt][1] = ld2bf(pl + 8 * 72);
            Al[mt][2] = ld2bf(pl + 8);   Al[mt][3] = ld2bf(pl + 8 * 72 + 8);
        }
#pragma unroll
        for (int nt = 0; nt < 6; nt++) {
            int co = wc * 48 + nt * 8 + r4;
            uint32_t Bh[2], Bl[2];
            const __nv_bfloat16* pb = sBh + co * 72 + col;
            const __nv_bfloat16* pc = sBl + co * 72 + col;
            Bh[0] = ld2bf(pb); Bh[1] = ld2bf(pb + 8);
            Bl[0] = ld2bf(pc); Bl[1] = ld2bf(pc + 8);
#pragma unroll
            for (int mt = 0; mt < 2; mt++) {
                mma16816(acc[mt][nt], Ah[mt], Bh);
                mma16816(acc[mt][nt], Ah[mt], Bl);
                mma16816(acc[mt][nt], Al[mt], Bh);
            }
        }
    }

    float* C = d_xp2 + (size_t)f * BB * TT * 96 + (size_t)r0 * 96;
#pragma unroll
    for (int nt = 0; nt < 6; nt++) {
        int co = wc * 48 + nt * 8 + q4;
        float b0 = bih2[f * 96 + co], b1 = bih2[f * 96 + co + 1];
#pragma unroll
        for (int mt = 0; mt < 2; mt++) {
            int r = wt * 32 + mt * 16 + r4;
            float2 v0 = make_float2(acc[mt][nt][0] + b0, acc[mt][nt][1] + b1);
            float2 v1 = make_float2(acc[mt][nt][2] + b0, acc[mt][nt][3] + b1);
            *(float2*)&C[(size_t)r * 96 + co] = v0;
            *(float2*)&C[(size_t)(r + 8) * 96 + co] = v1;
        }
    }
}

// ---------------- g2 recurrence: ILP-1, 2048 warps + 1-step prefetch; split-store v2 ----------------
__global__ __launch_bounds__(256, 2) void k_g2(const float* __restrict__ Whh2,
                                               const float* __restrict__ bhh2) {
    int gw = (blockIdx.x * 256 + threadIdx.x) >> 5;   // 0..2047
    int l  = threadIdx.x & 31;
    int b = gw & (BB - 1);
    int f = gw >> 7;

    float wr[32], wz[32], wn[32];
    const float* Wr = Whh2 + (size_t)(f * 96 + l) * 32;
    const float* Wz = Whh2 + (size_t)(f * 96 + 32 + l) * 32;
    const float* Wn = Whh2 + (size_t)(f * 96 + 64 + l) * 32;
#pragma unroll
    for (int k = 0; k < 32; k++) { wr[k] = Wr[k]; wz[k] = Wz[k]; wn[k] = Wn[k]; }
    float cr = bhh2[f * 96 + l], cz = bhh2[f * 96 + 32 + l], cn = bhh2[f * 96 + 64 + l];

    float h = 0.0f;
    const float* XP = d_xp2 + ((size_t)f * BB + b) * TT * 96;
    __nv_bfloat16* Vh = d_v2h + ((size_t)f * BB + b) * TT * 32 + l;
    __nv_bfloat16* Vl = d_v2l + ((size_t)f * BB + b) * TT * 32 + l;

    float xr = XP[l], xz = XP[32 + l], xn = XP[64 + l];

    for (int t = 0; t < TT; t++) {
        float xr_n = 0.0f, xz_n = 0.0f, xn_n = 0.0f;
        if (t + 1 < TT) {
            const float* xt_n = XP + (size_t)(t + 1) * 96;
            xr_n = xt_n[l];
            xz_n = xt_n[32 + l];
            xn_n = xt_n[64 + l];
        }
        float ar = cr, az = cz, an = cn;
#pragma unroll
        for (int k = 0; k < 32; k++) {
            float hk = __shfl_sync(0xffffffffu, h, k);
            ar += hk * wr[k];
            az += hk * wz[k];
            an += hk * wn[k];
        }
        float r = sigmoidf_(xr + ar);
        float z = sigmoidf_(xz + az);
        float n = tanhf_(xn + r * an);
        h = (1.0f - z) * n + z * h;
        __nv_bfloat16 hh, hl;
        split_bf16(h, hh, hl);
        Vh[(size_t)t * 32] = hh;
        Vl[(size_t)t * 32] = hl;
        xr = xr_n; xz = xz_n; xn = xn_n;
    }
}

// ---------------- convT 32->64, TC; A via cp.async of pre-split v2; split-store a3 ----------------
__global__ __launch_bounds__(256) void k_conv3_tc(const float* __restrict__ b3) {
    extern __shared__ __nv_bfloat16 sm3[];
    __nv_bfloat16* sxh = sm3;
    __nv_bfloat16* sxl = sm3 + 132 * 40;
    __nv_bfloat16* sbh = sm3 + 2 * 132 * 40;
    __nv_bfloat16* sbl = sbh + 64 * 168;

    int f = blockIdx.z, b = blockIdx.y, t0 = blockIdx.x * 128;
    int tid = threadIdx.x;
    int wid = tid >> 5, l = tid & 31;
    int wt = wid >> 1, wc = wid & 1;

    for (int i = tid; i < 2560; i += 256) {
        int split = i / 1280;
        int r = i % 1280;
        int co = r / 20, seg = r % 20;
        const __nv_bfloat16* src = (split ? d_w3l : d_w3h) + ((size_t)(f * 64 + co)) * 160 + seg * 8;
        __nv_bfloat16* dst = (split ? sbl : sbh) + co * 168 + seg * 8;
        cp16(dst, src);
    }

    // A: 132 rows x 32 ci, each row = 4 chunks of 8 bf16 per split
    const __nv_bfloat16* Xh = d_v2h + ((size_t)f * BB + b) * TT * 32;
    const __nv_bfloat16* Xl = d_v2l + ((size_t)f * BB + b) * TT * 32;
    for (int i = tid; i < 132 * 4; i += 256) {
        int tt = i >> 2, c = i & 3;
        int t = t0 - 2 + tt;
        __nv_bfloat16* dh = sxh + tt * 40 + c * 8;
        __nv_bfloat16* dl = sxl + tt * 40 + c * 8;
        if (t >= 0 && t < TT) {
            cp16(dh, Xh + (size_t)t * 32 + c * 8);
            cp16(dl, Xl + (size_t)t * 32 + c * 8);
        } else {
            *(uint4*)dh = make_uint4(0, 0, 0, 0);
            *(uint4*)dl = make_uint4(0, 0, 0, 0);
        }
    }
    CP_COMMIT();
    CP_WAIT0();
    __syncthreads();

    float acc[2][4][4];
#pragma unroll
    for (int mt = 0; mt < 2; mt++)
#pragma unroll
        for (int nt = 0; nt < 4; nt++)
#pragma unroll
            for (int q = 0; q < 4; q++) acc[mt][nt][q] = 0.0f;

    int q4 = 2 * (l & 3);
    int r4 = l >> 2;

#pragma unroll
    for (int s = 0; s < 10; s++) {
        int kp = s >> 1;
        int col = (s & 1) * 16 + q4;
        uint32_t Ah[2][4], Al[2][4];
#pragma unroll
        for (int mt = 0; mt < 2; mt++) {
            int row = wt * 32 + mt * 16 + r4 + kp;
            const __nv_bfloat16* ph = sxh + row * 40 + col;
            const __nv_bfloat16* pl = sxl + row * 40 + col;
            Ah[mt][0] = ld2bf(ph);            Ah[mt][1] = ld2bf(ph + 8 * 40);
            Ah[mt][2] = ld2bf(ph + 8);        Ah[mt][3] = ld2bf(ph + 8 * 40 + 8);
            Al[mt][0] = ld2bf(pl);            Al[mt][1] = ld2bf(pl + 8 * 40);
            Al[mt][2] = ld2bf(pl + 8);        Al[mt][3] = ld2bf(pl + 8 * 40 + 8);
        }
        int bk = s * 16 + q4;
#pragma unroll
        for (int nt = 0; nt < 4; nt++) {
            int co = wc * 32 + nt * 8 + r4;
            uint32_t Bh[2], Bl[2];
            const __nv_bfloat16* pb = sbh + co * 168 + bk;
            const __nv_bfloat16* pc = sbl + co * 168 + bk;
            Bh[0] = ld2bf(pb); Bh[1] = ld2bf(pb + 8);
            Bl[0] = ld2bf(pc); Bl[1] = ld2bf(pc + 8);
#pragma unroll
            for (int mt = 0; mt < 2; mt++) {
                mma16816(acc[mt][nt], Ah[mt], Bh);
                mma16816(acc[mt][nt], Ah[mt], Bl);
                mma16816(acc[mt][nt], Al[mt], Bh);
            }
        }
    }

    // epilogue: bias + leaky, split, store bf16 pairs
    __nv_bfloat16* Yh = d_a3h + (((size_t)f * BB + b) * TT + t0) * 64;
    __nv_bfloat16* Yl = d_a3l + (((size_t)f * BB + b) * TT + t0) * 64;
#pragma unroll
    for (int nt = 0; nt < 4; nt++) {
        int co = wc * 32 + nt * 8 + q4;
        float b0 = b3[f * 64 + co], b1 = b3[f * 64 + co + 1];
#pragma unroll
        for (int mt = 0; mt < 2; mt++) {
            int t = wt * 32 + mt * 16 + r4;
            float y0 = leaky_(acc[mt][nt][0] + b0);
            float y1 = leaky_(acc[mt][nt][1] + b1);
            float y2 = leaky_(acc[mt][nt][2] + b0);
            float y3 = leaky_(acc[mt][nt][3] + b1);
            __nv_bfloat16 h0, l0, h1, l1, h2, l2, h3, l3;
            split_bf16(y0, h0, l0);
            split_bf16(y1, h1, l1);
            split_bf16(y2, h2, l2);
            split_bf16(y3, h3, l3);
            *(uint32_t*)&Yh[(size_t)t * 64 + co]       = pack2(h0, h1);
            *(uint32_t*)&Yl[(size_t)t * 64 + co]       = pack2(l0, l1);
            *(uint32_t*)&Yh[(size_t)(t + 8) * 64 + co] = pack2(h2, h3);
            *(uint32_t*)&Yl[(size_t)(t + 8) * 64 + co] = pack2(l2, l3);
        }
    }
}

// ---------------- convT 64->128, TC; A via cp.async of pre-split a3 ----------------
__global__ __launch_bounds__(256) void k_conv2_tc(const float* __restrict__ b2) {
    extern __shared__ __nv_bfloat16 sm2[];
    __nv_bfloat16* sxh = sm2;
    __nv_bfloat16* sxl = sm2 + 132 * 72;
    __nv_bfloat16* sbb = sm2 + 2 * 132 * 72;

    int f = blockIdx.z, b = blockIdx.y, t0 = blockIdx.x * 128;
    int tid = threadIdx.x;
    int wid = tid >> 5, l = tid & 31;
    int wt = wid >> 1, wc = wid & 1;

    int lco = tid >> 1, lhalf = tid & 1;
    const __nv_bfloat16* wsrc_h = d_w2h + ((size_t)f * 128 + lco) * 320 + lhalf * 8;
    const __nv_bfloat16* wsrc_l = d_w2l + ((size_t)f * 128 + lco) * 320 + lhalf * 8;
    __nv_bfloat16* wdst0 = sbb + lco * 24 + lhalf * 8;

    cp16(wdst0,        wsrc_h);
    cp16(wdst0 + 3072, wsrc_l);

    // A: 132 rows x 64 ci, each row = 8 chunks of 8 bf16 per split
    const __nv_bfloat16* Xh = d_a3h + ((size_t)f * BB + b) * TT * 64;
    const __nv_bfloat16* Xl = d_a3l + ((size_t)f * BB + b) * TT * 64;
    for (int i = tid; i < 132 * 8; i += 256) {
        int tt = i >> 3, c = i & 7;
        int t = t0 - 2 + tt;
        __nv_bfloat16* dh = sxh + tt * 72 + c * 8;
        __nv_bfloat16* dl = sxl + tt * 72 + c * 8;
        if (t >= 0 && t < TT) {
            cp16(dh, Xh + (size_t)t * 64 + c * 8);
            cp16(dl, Xl + (size_t)t * 64 + c * 8);
        } else {
            *(uint4*)dh = make_uint4(0, 0, 0, 0);
            *(uint4*)dl = make_uint4(0, 0, 0, 0);
        }
    }
    CP_COMMIT();

    float acc[2][8][4];
#pragma unroll
    for (int mt = 0; mt < 2; mt++)
#pragma unroll
        for (int nt = 0; nt < 8; nt++)
#pragma unroll
            for (int q = 0; q < 4; q++) acc[mt][nt][q] = 0.0f;

    int q4 = 2 * (l & 3);
    int r4 = l >> 2;

    for (int s = 0; s < 20; s++) {
        if (s + 1 < 20) {
            __nv_bfloat16* wdst = sbb + ((s + 1) & 1) * 6144 + lco * 24 + lhalf * 8;
            cp16(wdst,        wsrc_h + (s + 1) * 16);
            cp16(wdst + 3072, wsrc_l + (s + 1) * 16);
        }
        CP_COMMIT();
        CP_WAIT1();
        __syncthreads();

        const __nv_bfloat16* sbh = sbb + (s & 1) * 6144;
        const __nv_bfloat16* sbl = sbh + 3072;
        int kp = s >> 2;
        int col = (s & 3) * 16 + q4;

        uint32_t Ah[2][4], Al[2][4];
#pragma unroll
        for (int mt = 0; mt < 2; mt++) {
            int row = wt * 32 + mt * 16 + r4 + kp;
            const __nv_bfloat16* ph = sxh + row * 72 + col;
            const __nv_bfloat16* pl = sxl + row * 72 + col;
            Ah[mt][0] = ld2bf(ph);            Ah[mt][1] = ld2bf(ph + 8 * 72);
            Ah[mt][2] = ld2bf(ph + 8);        Ah[mt][3] = ld2bf(ph + 8 * 72 + 8);
            Al[mt][0] = ld2bf(pl);            Al[mt][1] = ld2bf(pl + 8 * 72);
            Al[mt][2] = ld2bf(pl + 8);        Al[mt][3] = ld2bf(pl + 8 * 72 + 8);
        }
#pragma unroll
        for (int nt = 0; nt < 8; nt++) {
            int co = wc * 64 + nt * 8 + r4;
            uint32_t Bh[2], Bl[2];
            const __nv_bfloat16* pb = sbh + co * 24 + q4;
            const __nv_bfloat16* pc = sbl + co * 24 + q4;
            Bh[0] = ld2bf(pb); Bh[1] = ld2bf(pb + 8);
            Bl[0] = ld2bf(pc); Bl[1] = ld2bf(pc + 8);
#pragma unroll
            for (int mt = 0; mt < 2; mt++) {
                mma16816(acc[mt][nt], Ah[mt], Bh);
                mma16816(acc[mt][nt], Ah[mt], Bl);
                mma16816(acc[mt][nt], Al[mt], Bh);
            }
        }
        __syncthreads();
    }

    float* Y = d_a2 + (((size_t)f * BB + b) * TT + t0) * 128;
#pragma unroll
    for (int nt = 0; nt < 8; nt++) {
        int co = wc * 64 + nt * 8 + q4;
        float b0 = b2[f * 128 + co], b1v = b2[f * 128 + co + 1];
#pragma unroll
        for (int mt = 0; mt < 2; mt++) {
            int t = wt * 32 + mt * 16 + r4;
            float2 v0 = make_float2(leaky_(acc[mt][nt][0] + b0), leaky_(acc[mt][nt][1] + b1v));
            float2 v1 = make_float2(leaky_(acc[mt][nt][2] + b0), leaky_(acc[mt][nt][3] + b1v));
            *(float2*)&Y[(size_t)t * 128 + co] = v0;
            *(float2*)&Y[(size_t)(t + 8) * 128 + co] = v1;
        }
    }
}

// ---------------- convT 128 -> 1 + leaky, write final output ----------------
__global__ __launch_bounds__(64) void k_conv1(const float* __restrict__ w1,
                                              const float* __restrict__ b1,
                                              float* __restrict__ out) {
    __shared__ float sx[68][132];
    __shared__ float sw[5][128];
    int f = blockIdx.z, bb = blockIdx.y, t0 = blockIdx.x * 64;
    int tid = threadIdx.x;

    const float* X = d_a2 + ((size_t)f * BB + bb) * TT * 128;
    for (int i = tid; i < 68 * 128; i += 64) {
        int tt = i >> 7, ci = i & 127;
        int t = t0 - 2 + tt;
        sx[tt][ci] = (t >= 0 && t < TT) ? X[(size_t)t * 128 + ci] : 0.0f;
    }
    for (int i = tid; i < 5 * 128; i += 64) {
        int j = i >> 7, ci = i & 127;
        sw[j][ci] = w1[f * 640 + ci * 5 + (4 - j)];
    }
    __syncthreads();

    int tl = tid;
    float a0 = 0.0f, a1 = 0.0f, a2s = 0.0f, a3s = 0.0f;
#pragma unroll
    for (int j = 0; j < 5; j++) {
        const float* xr = &sx[tl + j][0];
        const float* wr_ = &sw[j][0];
#pragma unroll
        for (int ci = 0; ci < 128; ci += 4) {
            float4 a = *(const float4*)&xr[ci];
            float4 w = *(const float4*)&wr_[ci];
            a0 += a.x * w.x;
            a1 += a.y * w.y;
            a2s += a.z * w.z;
            a3s += a.w * w.w;
        }
    }
    float v = leaky_((a0 + a1) + (a2s + a3s) + b1[f]);
    out[((size_t)bb * TT + t0 + tl) * FF + f] = v;
}

// ---------------- launch ----------------
extern "C" void kernel_launch(void* const* d_in, const int* in_sizes, int n_in,
                              void* d_out, int out_size) {
    const float* x        = (const float*)d_in[0];
    const float* enc_Wih  = (const float*)d_in[1];
    const float* enc_Whh  = (const float*)d_in[2];
    const float* enc_bih  = (const float*)d_in[3];
    const float* enc_bhh  = (const float*)d_in[4];
    const float* g1_Wih_f = (const float*)d_in[5];
    const float* g1_Whh_f = (const float*)d_in[6];
    const float* g1_bih_f = (const float*)d_in[7];
    const float* g1_bhh_f = (const float*)d_in[8];
    const float* g1_Wih_b = (const float*)d_in[9];
    const float* g1_Whh_b = (const float*)d_in[10];
    const float* g1_bih_b = (const float*)d_in[11];
    const float* g1_bhh_b = (const float*)d_in[12];
    const float* g2_Wih   = (const float*)d_in[13];
    const float* g2_Whh   = (const float*)d_in[14];
    const float* g2_bih   = (const float*)d_in[15];
    const float* g2_bhh   = (const float*)d_in[16];
    const float* w3       = (const float*)d_in[17];
    const float* b3       = (const float*)d_in[18];
    const float* w2       = (const float*)d_in[19];
    const float* b2       = (const float*)d_in[20];
    const float* w1       = (const float*)d_in[21];
    const float* b1       = (const float*)d_in[22];
    float* out = (float*)d_out;

    const int SMEM3 = (2 * 132 * 40 + 2 * 64 * 168) * 2;     // 64128 B
    const int SMEM2 = (2 * 132 * 72 + 4 * 128 * 24) * 2;     // 62592 B
    const int SMEMX = (2 * 128 * 72 + 2 * 96 * 72) * 2;      // 64512 B
    static bool attr_set = false;
    if (!attr_set) {
        cudaFuncSetAttribute(k_conv3_tc, cudaFuncAttributeMaxDynamicSharedMemorySize, SMEM3);
        cudaFuncSetAttribute(k_conv2_tc, cudaFuncAttributeMaxDynamicSharedMemorySize, SMEM2);
        cudaFuncSetAttribute(k_xp2_tc,  cudaFuncAttributeMaxDynamicSharedMemorySize, SMEMX);
        attr_set = true;
    }

    k_wprep<<<(16 * 64 * 160 + 16 * 128 * 320 + 255) / 256, 256>>>(w3, w2);
    k_enc_xp<<<(BB * TT * 48 + 255) / 256, 256>>>(x, enc_Wih, enc_bih);
    k_enc_rec<<<32, 128>>>(enc_Whh, enc_bhh);
    k_g1<<<256, 256>>>(g1_Wih_f, g1_Whh_f, g1_bih_f, g1_bhh_f,
                       g1_Wih_b, g1_Whh_b, g1_bih_b, g1_bhh_b);
    {
        dim3 g(BB * TT / 128, FF);
        k_xp2_tc<<<g, 256, SMEMX>>>(g2_Wih, g2_bih);
    }
    k_g2<<<256, 256>>>(g2_Whh, g2_bhh);
    {
        dim3 g(TT / 128, BB, FF);
        k_conv3_tc<<<g, 256, SMEM3>>>(b3);
        k_conv2_tc<<<g, 256, SMEM2>>>(b2);
    }
    {
        dim3 g(TT / 64, BB, FF);
        k_conv1<<<g, 64>>>(w1, b1, out);
    }
}

// round 16
// speedup vs baseline: 1.1966x; 1.1178x over previous
#include <cuda_runtime.h>
#include <cuda_bf16.h>
#include <math.h>
#include <stdint.h>

#define BB 128
#define TT 512
#define FF 16
#define HH 32

// ---------------- scratch ----------------
__device__ float d_xpe[BB * TT * 48];
__device__ float d_h  [BB * TT * FF];
__device__ __nv_bfloat16 d_u1h[(size_t)FF * BB * TT * 64];   // biGRU output, pre-split
__device__ __nv_bfloat16 d_u1l[(size_t)FF * BB * TT * 64];
__device__ float d_xp2[(size_t)FF * BB * TT * 96];
__device__ __nv_bfloat16 d_v2h[(size_t)FF * BB * TT * 32];   // g2 output, pre-split
__device__ __nv_bfloat16 d_v2l[(size_t)FF * BB * TT * 32];
__device__ __nv_bfloat16 d_a3h[(size_t)FF * BB * TT * 64];   // conv3 output, pre-split
__device__ __nv_bfloat16 d_a3l[(size_t)FF * BB * TT * 64];
__device__ float d_a2 [(size_t)FF * BB * TT * 128];

__device__ __nv_bfloat16 d_w3h[16 * 64 * 160];
__device__ __nv_bfloat16 d_w3l[16 * 64 * 160];
__device__ __nv_bfloat16 d_w2h[16 * 128 * 320];
__device__ __nv_bfloat16 d_w2l[16 * 128 * 320];
__device__ __nv_bfloat16 d_wx2h[16 * 96 * 64];               // xp2 B weights, pre-split
__device__ __nv_bfloat16 d_wx2l[16 * 96 * 64];

__device__ __forceinline__ float sigmoidf_(float x) {
    return 1.0f / (1.0f + __expf(-x));
}
__device__ __forceinline__ float tanhf_(float x) {
    float ax = fabsf(x);
    float e  = __expf(-2.0f * ax);
    float t  = (1.0f - e) / (1.0f + e);
    return copysignf(t, x);
}
__device__ __forceinline__ float leaky_(float v) {
    return v >= 0.0f ? v : 0.01f * v;
}

// ---------------- tensor-core helpers ----------------
__device__ __forceinline__ void mma16816(float* c, const uint32_t* a, const uint32_t* b) {
    asm volatile(
        "mma.sync.aligned.m16n8k16.row.col.f32.bf16.bf16.f32 "
        "{%0,%1,%2,%3},{%4,%5,%6,%7},{%8,%9},{%0,%1,%2,%3};"
        : "+f"(c[0]), "+f"(c[1]), "+f"(c[2]), "+f"(c[3])
        : "r"(a[0]), "r"(a[1]), "r"(a[2]), "r"(a[3]), "r"(b[0]), "r"(b[1]));
}
__device__ __forceinline__ uint32_t ld2bf(const __nv_bfloat16* p) {
    return *(const uint32_t*)p;
}
__device__ __forceinline__ void cp16(void* dst, const void* src) {
    uint32_t d = (uint32_t)__cvta_generic_to_shared(dst);
    asm volatile("cp.async.ca.shared.global [%0],[%1],16;" :: "r"(d), "l"(src));
}
#define CP_COMMIT() asm volatile("cp.async.commit_group;")
#define CP_WAIT0()  asm volatile("cp.async.wait_group 0;")
#define CP_WAIT1()  asm volatile("cp.async.wait_group 1;")

__device__ __forceinline__ void split_bf16(float v, __nv_bfloat16& hi, __nv_bfloat16& lo) {
    hi = __float2bfloat16(v);
    lo = __float2bfloat16(v - __bfloat162float(hi));
}
__device__ __forceinline__ uint32_t pack2(__nv_bfloat16 a, __nv_bfloat16 b) {
    __nv_bfloat162 t; t.x = a; t.y = b;
    return *(uint32_t*)&t;
}

// ---------------- weight pre-split (w3, w2, xp2-Wih) ----------------
__global__ void k_wprep(const float* __restrict__ w3, const float* __restrict__ w2,
                        const float* __restrict__ wx2) {
    int idx = blockIdx.x * blockDim.x + threadIdx.x;
    const int N3 = 16 * 64 * 160;
    const int N2 = 16 * 128 * 320;
    const int N4 = 16 * 96 * 64;
    if (idx < N3) {
        int f  = idx / (64 * 160);
        int r  = idx % (64 * 160);
        int co = r / 160;
        int k  = r % 160;
        int kp = k / 32, ci = k % 32;
        float v = w3[((size_t)(f * 32 + ci) * 64 + co) * 5 + (4 - kp)];
        split_bf16(v, d_w3h[idx], d_w3l[idx]);
    } else if (idx < N3 + N2) {
        int j  = idx - N3;
        int f  = j / (128 * 320);
        int r  = j % (128 * 320);
        int co = r / 320;
        int k  = r % 320;
        int kp = k / 64, ci = k % 64;
        float v = w2[((size_t)(f * 64 + ci) * 128 + co) * 5 + (4 - kp)];
        split_bf16(v, d_w2h[j], d_w2l[j]);
    } else if (idx < N3 + N2 + N4) {
        int j = idx - N3 - N2;
        split_bf16(wx2[j], d_wx2h[j], d_wx2l[j]);
    }
}

// ---------------- encoder input projection ----------------
__global__ void k_enc_xp(const float* __restrict__ x,
                         const float* __restrict__ Wih,
                         const float* __restrict__ bih) {
    int idx = blockIdx.x * blockDim.x + threadIdx.x;
    if (idx >= BB * TT * 48) return;
    int g  = idx % 48;
    int bt = idx / 48;
    int b  = bt / TT;
    int t  = bt % TT;
    float x0 = x[b * 2 * TT + t];
    float x1 = x[b * 2 * TT + TT + t];
    d_xpe[idx] = x0 * Wih[g * 2] + x1 * Wih[g * 2 + 1] + bih[g];
}

// ---------------- encoder GRU recurrence ----------------
__global__ void k_enc_rec(const float* __restrict__ Whh,
                          const float* __restrict__ bhh) {
    int warp = (blockIdx.x * blockDim.x + threadIdx.x) >> 5;
    int l    = threadIdx.x & 31;
    if (warp >= BB) return;
    int b = warp;

    float w0[16], w1[16];
#pragma unroll
    for (int k = 0; k < 16; k++) {
        w0[k] = Whh[l * 16 + k];
        w1[k] = (l < 16) ? Whh[(32 + l) * 16 + k] : 0.0f;
    }
    float bh0 = bhh[l];
    float bh1 = (l < 16) ? bhh[32 + l] : 0.0f;

    float h = 0.0f;
    const float* xp = d_xpe + (size_t)b * TT * 48;
    float* ho = d_h + (size_t)b * TT * FF;

    for (int t = 0; t < TT; t++) {
        float xpa = xp[t * 48 + l];
        float xpn = (l < 16) ? xp[t * 48 + 32 + l] : 0.0f;
        float a0 = bh0, a1 = bh1;
#pragma unroll
        for (int k = 0; k < 16; k++) {
            float hk = __shfl_sync(0xffffffffu, h, k);
            a0 += hk * w0[k];
            a1 += hk * w1[k];
        }
        float g = sigmoidf_(xpa + a0);
        float z = __shfl_sync(0xffffffffu, g, l + 16);
        if (l < 16) {
            float n = tanhf_(xpn + g * a1);
            h = (1.0f - z) * n + z * h;
            ho[t * FF + l] = h;
        }
    }
}

// ---------------- biGRU: ILP-1, rep-2 + xi prefetch; split-store u1 ----------------
__global__ __launch_bounds__(256, 2) void k_g1(
    const float* __restrict__ Wih_f, const float* __restrict__ Whh_f,
    const float* __restrict__ bih_f, const float* __restrict__ bhh_f,
    const float* __restrict__ Wih_b, const float* __restrict__ Whh_b,
    const float* __restrict__ bih_b, const float* __restrict__ bhh_b) {
    int gw0 = (blockIdx.x * 256 + threadIdx.x) >> 5;   // 0..2047
    int l   = threadIdx.x & 31;

    for (int rep = 0; rep < 2; rep++) {
        int gw  = gw0 + rep * 2048;                    // 0..4095
        int b   = gw & (BB - 1);
        int f   = (gw >> 7) & (FF - 1);
        int dir = gw >> 11;

        const float* Wih = dir ? Wih_b : Wih_f;
        const float* Whh = dir ? Whh_b : Whh_f;
        const float* bih = dir ? bih_b : bih_f;
        const float* bhh = dir ? bhh_b : bhh_f;

        float wr[32], wz[32], wn[32];
        const float* Wr = Whh + (size_t)(f * 96 + l) * 32;
        const float* Wz = Whh + (size_t)(f * 96 + 32 + l) * 32;
        const float* Wn = Whh + (size_t)(f * 96 + 64 + l) * 32;
#pragma unroll
        for (int k = 0; k < 32; k++) { wr[k] = Wr[k]; wz[k] = Wz[k]; wn[k] = Wn[k]; }

        float wir = Wih[f * 96 + l], wiz = Wih[f * 96 + 32 + l], win = Wih[f * 96 + 64 + l];
        float br  = bih[f * 96 + l], bz  = bih[f * 96 + 32 + l], bn  = bih[f * 96 + 64 + l];
        float cr  = bhh[f * 96 + l], cz  = bhh[f * 96 + 32 + l], cn  = bhh[f * 96 + 64 + l];

        float h = 0.0f;
        const float* hin = d_h + (size_t)b * TT * FF + f;
        __nv_bfloat16* uh = d_u1h + (size_t)(f * BB + b) * TT * 64 + dir * 32 + l;
        __nv_bfloat16* ul = d_u1l + (size_t)(f * BB + b) * TT * 64 + dir * 32 + l;

        int t0 = dir ? (TT - 1) : 0;
        float xi = hin[(size_t)t0 * FF];

        for (int s = 0; s < TT; s++) {
            int t  = dir ? (TT - 1 - s) : s;
            int tn = dir ? (TT - 2 - s) : (s + 1);
            float xi_n = (s + 1 < TT) ? hin[(size_t)tn * FF] : 0.0f;

            float ar = cr, az = cz, an = cn;
#pragma unroll
            for (int k = 0; k < 32; k++) {
                float hk = __shfl_sync(0xffffffffu, h, k);
                ar += hk * wr[k];
                az += hk * wz[k];
                an += hk * wn[k];
            }
            float r = sigmoidf_(xi * wir + br + ar);
            float z = sigmoidf_(xi * wiz + bz + az);
            float n = tanhf_(xi * win + bn + r * an);
            h = (1.0f - z) * n + z * h;
            __nv_bfloat16 hh, hl;
            split_bf16(h, hh, hl);
            uh[(size_t)t * 64] = hh;
            ul[(size_t)t * 64] = hl;
            xi = xi_n;
        }
    }
}

// ---------------- g2 input projection, TC; A and B via cp.async of pre-split data ----------------
__global__ __launch_bounds__(256) void k_xp2_tc(const float* __restrict__ bih2) {
    extern __shared__ __nv_bfloat16 smx[];
    __nv_bfloat16* sAh = smx;
    __nv_bfloat16* sAl = smx + 128 * 72;
    __nv_bfloat16* sBh = smx + 2 * 128 * 72;
    __nv_bfloat16* sBl = sBh + 96 * 72;

    int f  = blockIdx.y;
    int r0 = blockIdx.x * 128;
    int tid = threadIdx.x;
    int wid = tid >> 5, l = tid & 31;
    int wt = wid >> 1, wc = wid & 1;

    const __nv_bfloat16* Ah_ = d_u1h + (size_t)f * BB * TT * 64 + (size_t)r0 * 64;
    const __nv_bfloat16* Al_ = d_u1l + (size_t)f * BB * TT * 64 + (size_t)r0 * 64;
    const __nv_bfloat16* Bh_ = d_wx2h + (size_t)f * 96 * 64;
    const __nv_bfloat16* Bl_ = d_wx2l + (size_t)f * 96 * 64;

    // A: 128 rows x 64 cols, 8 chunks of 8 bf16 per row per split
    for (int i = tid; i < 128 * 8; i += 256) {
        int rr = i >> 3, c = i & 7;
        cp16(sAh + rr * 72 + c * 8, Ah_ + (size_t)rr * 64 + c * 8);
        cp16(sAl + rr * 72 + c * 8, Al_ + (size_t)rr * 64 + c * 8);
    }
    // B: 96 rows x 64 cols
    for (int i = tid; i < 96 * 8; i += 256) {
        int j = i >> 3, c = i & 7;
        cp16(sBh + j * 72 + c * 8, Bh_ + (size_t)j * 64 + c * 8);
        cp16(sBl + j * 72 + c * 8, Bl_ + (size_t)j * 64 + c * 8);
    }
    CP_COMMIT();
    CP_WAIT0();
    __syncthreads();

    float acc[2][6][4];
#pragma unroll
    for (int mt = 0; mt < 2; mt++)
#pragma unroll
        for (int nt = 0; nt < 6; nt++)
#pragma unroll
            for (int q = 0; q < 4; q++) acc[mt][nt][q] = 0.0f;

    int q4 = 2 * (l & 3);
    int r4 = l >> 2;

#pragma unroll
    for (int kt = 0; kt < 4; kt++) {
        int col = kt * 16 + q4;
        uint32_t Ah[2][4], Al[2][4];
#pragma unroll
        for (int mt = 0; mt < 2; mt++) {
            int row = wt * 32 + mt * 16 + r4;
            const __nv_bfloat16* ph = sAh + row * 72 + col;
            const __nv_bfloat16* pl = sAl + row * 72 + col;
            Ah[mt][0] = ld2bf(ph);       Ah[mt][1] = ld2bf(ph + 8 * 72);
            Ah[mt][2] = ld2bf(ph + 8);   Ah[mt][3] = ld2bf(ph + 8 * 72 + 8);
            Al[mt][0] = ld2bf(pl);       Al[mt][1] = ld2bf(pl + 8 * 72);
            Al[mt][2] = ld2bf(pl + 8);   Al[mt][3] = ld2bf(pl + 8 * 72 + 8);
        }
#pragma unroll
        for (int nt = 0; nt < 6; nt++) {
            int co = wc * 48 + nt * 8 + r4;
            uint32_t Bh[2], Bl[2];
            const __nv_bfloat16* pb = sBh + co * 72 + col;
            const __nv_bfloat16* pc = sBl + co * 72 + col;
            Bh[0] = ld2bf(pb); Bh[1] = ld2bf(pb + 8);
            Bl[0] = ld2bf(pc); Bl[1] = ld2bf(pc + 8);
#pragma unroll
            for (int mt = 0; mt < 2; mt++) {
                mma16816(acc[mt][nt], Ah[mt], Bh);
                mma16816(acc[mt][nt], Ah[mt], Bl);
                mma16816(acc[mt][nt], Al[mt], Bh);
            }
        }
    }

    float* C = d_xp2 + (size_t)f * BB * TT * 96 + (size_t)r0 * 96;
#pragma unroll
    for (int nt = 0; nt < 6; nt++) {
        int co = wc * 48 + nt * 8 + q4;
        float b0 = bih2[f * 96 + co], b1 = bih2[f * 96 + co + 1];
#pragma unroll
        for (int mt = 0; mt < 2; mt++) {
            int r = wt * 32 + mt * 16 + r4;
            float2 v0 = make_float2(acc[mt][nt][0] + b0, acc[mt][nt][1] + b1);
            float2 v1 = make_float2(acc[mt][nt][2] + b0, acc[mt][nt][3] + b1);
            *(float2*)&C[(size_t)r * 96 + co] = v0;
            *(float2*)&C[(size_t)(r + 8) * 96 + co] = v1;
        }
    }
}

// ---------------- g2 recurrence: ILP-1, 2048 warps + prefetch; split-store v2 ----------------
__global__ __launch_bounds__(256, 2) void k_g2(const float* __restrict__ Whh2,
                                               const float* __restrict__ bhh2) {
    int gw = (blockIdx.x * 256 + threadIdx.x) >> 5;   // 0..2047
    int l  = threadIdx.x & 31;
    int b = gw & (BB - 1);
    int f = gw >> 7;

    float wr[32], wz[32], wn[32];
    const float* Wr = Whh2 + (size_t)(f * 96 + l) * 32;
    const float* Wz = Whh2 + (size_t)(f * 96 + 32 + l) * 32;
    const float* Wn = Whh2 + (size_t)(f * 96 + 64 + l) * 32;
#pragma unroll
    for (int k = 0; k < 32; k++) { wr[k] = Wr[k]; wz[k] = Wz[k]; wn[k] = Wn[k]; }
    float cr = bhh2[f * 96 + l], cz = bhh2[f * 96 + 32 + l], cn = bhh2[f * 96 + 64 + l];

    float h = 0.0f;
    const float* XP = d_xp2 + ((size_t)f * BB + b) * TT * 96;
    __nv_bfloat16* Vh = d_v2h + ((size_t)f * BB + b) * TT * 32 + l;
    __nv_bfloat16* Vl = d_v2l + ((size_t)f * BB + b) * TT * 32 + l;

    float xr = XP[l], xz = XP[32 + l], xn = XP[64 + l];

    for (int t = 0; t < TT; t++) {
        float xr_n = 0.0f, xz_n = 0.0f, xn_n = 0.0f;
        if (t + 1 < TT) {
            const float* xt_n = XP + (size_t)(t + 1) * 96;
            xr_n = xt_n[l];
            xz_n = xt_n[32 + l];
            xn_n = xt_n[64 + l];
        }
        float ar = cr, az = cz, an = cn;
#pragma unroll
        for (int k = 0; k < 32; k++) {
            float hk = __shfl_sync(0xffffffffu, h, k);
            ar += hk * wr[k];
            az += hk * wz[k];
            an += hk * wn[k];
        }
        float r = sigmoidf_(xr + ar);
        float z = sigmoidf_(xz + az);
        float n = tanhf_(xn + r * an);
        h = (1.0f - z) * n + z * h;
        __nv_bfloat16 hh, hl;
        split_bf16(h, hh, hl);
        Vh[(size_t)t * 32] = hh;
        Vl[(size_t)t * 32] = hl;
        xr = xr_n; xz = xz_n; xn = xn_n;
    }
}

// ---------------- convT 32->64, TC; A via cp.async; split-store a3 ----------------
__global__ __launch_bounds__(256) void k_conv3_tc(const float* __restrict__ b3) {
    extern __shared__ __nv_bfloat16 sm3[];
    __nv_bfloat16* sxh = sm3;
    __nv_bfloat16* sxl = sm3 + 132 * 40;
    __nv_bfloat16* sbh = sm3 + 2 * 132 * 40;
    __nv_bfloat16* sbl = sbh + 64 * 168;

    int f = blockIdx.z, b = blockIdx.y, t0 = blockIdx.x * 128;
    int tid = threadIdx.x;
    int wid = tid >> 5, l = tid & 31;
    int wt = wid >> 1, wc = wid & 1;

    for (int i = tid; i < 2560; i += 256) {
        int split = i / 1280;
        int r = i % 1280;
        int co = r / 20, seg = r % 20;
        const __nv_bfloat16* src = (split ? d_w3l : d_w3h) + ((size_t)(f * 64 + co)) * 160 + seg * 8;
        __nv_bfloat16* dst = (split ? sbl : sbh) + co * 168 + seg * 8;
        cp16(dst, src);
    }

    const __nv_bfloat16* Xh = d_v2h + ((size_t)f * BB + b) * TT * 32;
    const __nv_bfloat16* Xl = d_v2l + ((size_t)f * BB + b) * TT * 32;
    for (int i = tid; i < 132 * 4; i += 256) {
        int tt = i >> 2, c = i & 3;
        int t = t0 - 2 + tt;
        __nv_bfloat16* dh = sxh + tt * 40 + c * 8;
        __nv_bfloat16* dl = sxl + tt * 40 + c * 8;
        if (t >= 0 && t < TT) {
            cp16(dh, Xh + (size_t)t * 32 + c * 8);
            cp16(dl, Xl + (size_t)t * 32 + c * 8);
        } else {
            *(uint4*)dh = make_uint4(0, 0, 0, 0);
            *(uint4*)dl = make_uint4(0, 0, 0, 0);
        }
    }
    CP_COMMIT();
    CP_WAIT0();
    __syncthreads();

    float acc[2][4][4];
#pragma unroll
    for (int mt = 0; mt < 2; mt++)
#pragma unroll
        for (int nt = 0; nt < 4; nt++)
#pragma unroll
            for (int q = 0; q < 4; q++) acc[mt][nt][q] = 0.0f;

    int q4 = 2 * (l & 3);
    int r4 = l >> 2;

#pragma unroll
    for (int s = 0; s < 10; s++) {
        int kp = s >> 1;
        int col = (s & 1) * 16 + q4;
        uint32_t Ah[2][4], Al[2][4];
#pragma unroll
        for (int mt = 0; mt < 2; mt++) {
            int row = wt * 32 + mt * 16 + r4 + kp;
            const __nv_bfloat16* ph = sxh + row * 40 + col;
            const __nv_bfloat16* pl = sxl + row * 40 + col;
            Ah[mt][0] = ld2bf(ph);            Ah[mt][1] = ld2bf(ph + 8 * 40);
            Ah[mt][2] = ld2bf(ph + 8);        Ah[mt][3] = ld2bf(ph + 8 * 40 + 8);
            Al[mt][0] = ld2bf(pl);            Al[mt][1] = ld2bf(pl + 8 * 40);
            Al[mt][2] = ld2bf(pl + 8);        Al[mt][3] = ld2bf(pl + 8 * 40 + 8);
        }
        int bk = s * 16 + q4;
#pragma unroll
        for (int nt = 0; nt < 4; nt++) {
            int co = wc * 32 + nt * 8 + r4;
            uint32_t Bh[2], Bl[2];
            const __nv_bfloat16* pb = sbh + co * 168 + bk;
            const __nv_bfloat16* pc = sbl + co * 168 + bk;
            Bh[0] = ld2bf(pb); Bh[1] = ld2bf(pb + 8);
            Bl[0] = ld2bf(pc); Bl[1] = ld2bf(pc + 8);
#pragma unroll
            for (int mt = 0; mt < 2; mt++) {
                mma16816(acc[mt][nt], Ah[mt], Bh);
                mma16816(acc[mt][nt], Ah[mt], Bl);
                mma16816(acc[mt][nt], Al[mt], Bh);
            }
        }
    }

    __nv_bfloat16* Yh = d_a3h + (((size_t)f * BB + b) * TT + t0) * 64;
    __nv_bfloat16* Yl = d_a3l + (((size_t)f * BB + b) * TT + t0) * 64;
#pragma unroll
    for (int nt = 0; nt < 4; nt++) {
        int co = wc * 32 + nt * 8 + q4;
        float b0 = b3[f * 64 + co], b1 = b3[f * 64 + co + 1];
#pragma unroll
        for (int mt = 0; mt < 2; mt++) {
            int t = wt * 32 + mt * 16 + r4;
            float y0 = leaky_(acc[mt][nt][0] + b0);
            float y1 = leaky_(acc[mt][nt][1] + b1);
            float y2 = leaky_(acc[mt][nt][2] + b0);
            float y3 = leaky_(acc[mt][nt][3] + b1);
            __nv_bfloat16 h0, l0, h1, l1, h2, l2, h3, l3;
            split_bf16(y0, h0, l0);
            split_bf16(y1, h1, l1);
            split_bf16(y2, h2, l2);
            split_bf16(y3, h3, l3);
            *(uint32_t*)&Yh[(size_t)t * 64 + co]       = pack2(h0, h1);
            *(uint32_t*)&Yl[(size_t)t * 64 + co]       = pack2(l0, l1);
            *(uint32_t*)&Yh[(size_t)(t + 8) * 64 + co] = pack2(h2, h3);
            *(uint32_t*)&Yl[(size_t)(t + 8) * 64 + co] = pack2(l2, l3);
        }
    }
}

// ---------------- convT 64->128, TC; A via cp.async of pre-split a3 ----------------
__global__ __launch_bounds__(256) void k_conv2_tc(const float* __restrict__ b2) {
    extern __shared__ __nv_bfloat16 sm2[];
    __nv_bfloat16* sxh = sm2;
    __nv_bfloat16* sxl = sm2 + 132 * 72;
    __nv_bfloat16* sbb = sm2 + 2 * 132 * 72;

    int f = blockIdx.z, b = blockIdx.y, t0 = blockIdx.x * 128;
    int tid = threadIdx.x;
    int wid = tid >> 5, l = tid & 31;
    int wt = wid >> 1, wc = wid & 1;

    int lco = tid >> 1, lhalf = tid & 1;
    const __nv_bfloat16* wsrc_h = d_w2h + ((size_t)f * 128 + lco) * 320 + lhalf * 8;
    const __nv_bfloat16* wsrc_l = d_w2l + ((size_t)f * 128 + lco) * 320 + lhalf * 8;
    __nv_bfloat16* wdst0 = sbb + lco * 24 + lhalf * 8;

    cp16(wdst0,        wsrc_h);
    cp16(wdst0 + 3072, wsrc_l);

    const __nv_bfloat16* Xh = d_a3h + ((size_t)f * BB + b) * TT * 64;
    const __nv_bfloat16* Xl = d_a3l + ((size_t)f * BB + b) * TT * 64;
    for (int i = tid; i < 132 * 8; i += 256) {
        int tt = i >> 3, c = i & 7;
        int t = t0 - 2 + tt;
        __nv_bfloat16* dh = sxh + tt * 72 + c * 8;
        __nv_bfloat16* dl = sxl + tt * 72 + c * 8;
        if (t >= 0 && t < TT) {
            cp16(dh, Xh + (size_t)t * 64 + c * 8);
            cp16(dl, Xl + (size_t)t * 64 + c * 8);
        } else {
            *(uint4*)dh = make_uint4(0, 0, 0, 0);
            *(uint4*)dl = make_uint4(0, 0, 0, 0);
        }
    }
    CP_COMMIT();

    float acc[2][8][4];
#pragma unroll
    for (int mt = 0; mt < 2; mt++)
#pragma unroll
        for (int nt = 0; nt < 8; nt++)
#pragma unroll
            for (int q = 0; q < 4; q++) acc[mt][nt][q] = 0.0f;

    int q4 = 2 * (l & 3);
    int r4 = l >> 2;

    for (int s = 0; s < 20; s++) {
        if (s + 1 < 20) {
            __nv_bfloat16* wdst = sbb + ((s + 1) & 1) * 6144 + lco * 24 + lhalf * 8;
            cp16(wdst,        wsrc_h + (s + 1) * 16);
            cp16(wdst + 3072, wsrc_l + (s + 1) * 16);
        }
        CP_COMMIT();
        CP_WAIT1();
        __syncthreads();

        const __nv_bfloat16* sbh = sbb + (s & 1) * 6144;
        const __nv_bfloat16* sbl = sbh + 3072;
        int kp = s >> 2;
        int col = (s & 3) * 16 + q4;

        uint32_t Ah[2][4], Al[2][4];
#pragma unroll
        for (int mt = 0; mt < 2; mt++) {
            int row = wt * 32 + mt * 16 + r4 + kp;
            const __nv_bfloat16* ph = sxh + row * 72 + col;
            const __nv_bfloat16* pl = sxl + row * 72 + col;
            Ah[mt][0] = ld2bf(ph);            Ah[mt][1] = ld2bf(ph + 8 * 72);
            Ah[mt][2] = ld2bf(ph + 8);        Ah[mt][3] = ld2bf(ph + 8 * 72 + 8);
            Al[mt][0] = ld2bf(pl);            Al[mt][1] = ld2bf(pl + 8 * 72);
            Al[mt][2] = ld2bf(pl + 8);        Al[mt][3] = ld2bf(pl + 8 * 72 + 8);
        }
#pragma unroll
        for (int nt = 0; nt < 8; nt++) {
            int co = wc * 64 + nt * 8 + r4;
            uint32_t Bh[2], Bl[2];
            const __nv_bfloat16* pb = sbh + co * 24 + q4;
            const __nv_bfloat16* pc = sbl + co * 24 + q4;
            Bh[0] = ld2bf(pb); Bh[1] = ld2bf(pb + 8);
            Bl[0] = ld2bf(pc); Bl[1] = ld2bf(pc + 8);
#pragma unroll
            for (int mt = 0; mt < 2; mt++) {
                mma16816(acc[mt][nt], Ah[mt], Bh);
                mma16816(acc[mt][nt], Ah[mt], Bl);
                mma16816(acc[mt][nt], Al[mt], Bh);
            }
        }
        __syncthreads();
    }

    float* Y = d_a2 + (((size_t)f * BB + b) * TT + t0) * 128;
#pragma unroll
    for (int nt = 0; nt < 8; nt++) {
        int co = wc * 64 + nt * 8 + q4;
        float b0 = b2[f * 128 + co], b1v = b2[f * 128 + co + 1];
#pragma unroll
        for (int mt = 0; mt < 2; mt++) {
            int t = wt * 32 + mt * 16 + r4;
            float2 v0 = make_float2(leaky_(acc[mt][nt][0] + b0), leaky_(acc[mt][nt][1] + b1v));
            float2 v1 = make_float2(leaky_(acc[mt][nt][2] + b0), leaky_(acc[mt][nt][3] + b1v));
            *(float2*)&Y[(size_t)t * 128 + co] = v0;
            *(float2*)&Y[(size_t)(t + 8) * 128 + co] = v1;
        }
    }
}

// ---------------- convT 128 -> 1 + leaky, float4 loads ----------------
__global__ __launch_bounds__(64) void k_conv1(const float* __restrict__ w1,
                                              const float* __restrict__ b1,
                                              float* __restrict__ out) {
    __shared__ float sx[68][132];
    __shared__ float sw[5][128];
    int f = blockIdx.z, bb = blockIdx.y, t0 = blockIdx.x * 64;
    int tid = threadIdx.x;

    const float* X = d_a2 + ((size_t)f * BB + bb) * TT * 128;
    for (int i = tid; i < 68 * 32; i += 64) {
        int tt = i >> 5, c = i & 31;
        int t = t0 - 2 + tt;
        float4 v = (t >= 0 && t < TT) ? *(const float4*)&X[(size_t)t * 128 + c * 4]
                                      : make_float4(0.f, 0.f, 0.f, 0.f);
        *(float4*)&sx[tt][c * 4] = v;
    }
    for (int i = tid; i < 5 * 128; i += 64) {
        int j = i >> 7, ci = i & 127;
        sw[j][ci] = w1[f * 640 + ci * 5 + (4 - j)];
    }
    __syncthreads();

    int tl = tid;
    float a0 = 0.0f, a1 = 0.0f, a2s = 0.0f, a3s = 0.0f;
#pragma unroll
    for (int j = 0; j < 5; j++) {
        const float* xr = &sx[tl + j][0];
        const float* wr_ = &sw[j][0];
#pragma unroll
        for (int ci = 0; ci < 128; ci += 4) {
            float4 a = *(const float4*)&xr[ci];
            float4 w = *(const float4*)&wr_[ci];
            a0 += a.x * w.x;
            a1 += a.y * w.y;
            a2s += a.z * w.z;
            a3s += a.w * w.w;
        }
    }
    float v = leaky_((a0 + a1) + (a2s + a3s) + b1[f]);
    out[((size_t)bb * TT + t0 + tl) * FF + f] = v;
}

// ---------------- launch ----------------
extern "C" void kernel_launch(void* const* d_in, const int* in_sizes, int n_in,
                              void* d_out, int out_size) {
    const float* x        = (const float*)d_in[0];
    const float* enc_Wih  = (const float*)d_in[1];
    const float* enc_Whh  = (const float*)d_in[2];
    const float* enc_bih  = (const float*)d_in[3];
    const float* enc_bhh  = (const float*)d_in[4];
    const float* g1_Wih_f = (const float*)d_in[5];
    const float* g1_Whh_f = (const float*)d_in[6];
    const float* g1_bih_f = (const float*)d_in[7];
    const float* g1_bhh_f = (const float*)d_in[8];
    const float* g1_Wih_b = (const float*)d_in[9];
    const float* g1_Whh_b = (const float*)d_in[10];
    const float* g1_bih_b = (const float*)d_in[11];
    const float* g1_bhh_b = (const float*)d_in[12];
    const float* g2_Wih   = (const float*)d_in[13];
    const float* g2_Whh   = (const float*)d_in[14];
    const float* g2_bih   = (const float*)d_in[15];
    const float* g2_bhh   = (const float*)d_in[16];
    const float* w3       = (const float*)d_in[17];
    const float* b3       = (const float*)d_in[18];
    const float* w2       = (const float*)d_in[19];
    const float* b2       = (const float*)d_in[20];
    const float* w1       = (const float*)d_in[21];
    const float* b1       = (const float*)d_in[22];
    float* out = (float*)d_out;

    const int SMEM3 = (2 * 132 * 40 + 2 * 64 * 168) * 2;     // 64128 B
    const int SMEM2 = (2 * 132 * 72 + 4 * 128 * 24) * 2;     // 62592 B
    const int SMEMX = (2 * 128 * 72 + 2 * 96 * 72) * 2;      // 64512 B
    static bool attr_set = false;
    if (!attr_set) {
        cudaFuncSetAttribute(k_conv3_tc, cudaFuncAttributeMaxDynamicSharedMemorySize, SMEM3);
        cudaFuncSetAttribute(k_conv2_tc, cudaFuncAttributeMaxDynamicSharedMemorySize, SMEM2);
        cudaFuncSetAttribute(k_xp2_tc,  cudaFuncAttributeMaxDynamicSharedMemorySize, SMEMX);
        attr_set = true;
    }

    const int NW = 16 * 64 * 160 + 16 * 128 * 320 + 16 * 96 * 64;
    k_wprep<<<(NW + 255) / 256, 256>>>(w3, w2, g2_Wih);
    k_enc_xp<<<(BB * TT * 48 + 255) / 256, 256>>>(x, enc_Wih, enc_bih);
    k_enc_rec<<<32, 128>>>(enc_Whh, enc_bhh);
    k_g1<<<256, 256>>>(g1_Wih_f, g1_Whh_f, g1_bih_f, g1_bhh_f,
                       g1_Wih_b, g1_Whh_b, g1_bih_b, g1_bhh_b);
    {
        dim3 g(BB * TT / 128, FF);
        k_xp2_tc<<<g, 256, SMEMX>>>(g2_bih);
    }
    k_g2<<<256, 256>>>(g2_Whh, g2_bhh);
    {
        dim3 g(TT / 128, BB, FF);
        k_conv3_tc<<<g, 256, SMEM3>>>(b3);
        k_conv2_tc<<<g, 256, SMEM2>>>(b2);
    }
    {
        dim3 g(TT / 64, BB, FF);
        k_conv1<<<g, 64>>>(w1, b1, out);
    }
}